// round 12
// baseline (speedup 1.0000x reference)
#include <cuda_runtime.h>
#include <cuda_fp16.h>
#include <cstdint>
#include <cstring>

#define NPTS   400000
#define NXG    352
#define NYG    400
#define CANVAS 281600          // 2 * 1 * 400 * 352
#define BNEPS  1e-3f
#define NTILES (NPTS / 128)    // 3125

// ---------------- scratch (static __device__ — no allocation allowed) ----------------
static __device__ int      g_idx[NPTS];
static __device__ float    g_vsum[CANVAS * 3];
static __device__ float    g_vcnt[CANVAS];
static __device__ float    g_z0[(size_t)NPTS * 64];      // raw z0 (pre-BN)
static __device__ uint32_t g_enc0[(size_t)CANVAS * 64];  // enc(max raw z0) per voxel
static __device__ float    g_z1[(size_t)NPTS * 128];
static __device__ double   g_stats[512];                 // s0 q0 s1 q1
static __device__ float    g_ab[384];                    // a0 c0 a1 c1 (folded BN)

// ================= helpers =================
__device__ __forceinline__ uint32_t smem_u32(const void* p) {
    uint32_t a;
    asm("{ .reg .u64 t; cvta.to.shared.u64 t, %1; cvt.u32.u64 %0, t; }" : "=r"(a) : "l"(p));
    return a;
}
// monotone float <-> uint (total order); enc(x) == 0 only for untouched sentinel
__device__ __forceinline__ uint32_t encf(float x) {
    uint32_t b = __float_as_uint(x);
    return (b & 0x80000000u) ? ~b : (b | 0x80000000u);
}
__device__ __forceinline__ float decf(uint32_t u) {
    return __uint_as_float((u & 0x80000000u) ? (u & 0x7FFFFFFFu) : ~u);
}
__device__ __forceinline__ void ldsm_x4(uint32_t* r, uint32_t addr) {
    asm volatile("ldmatrix.sync.aligned.m8n8.x4.shared.b16 {%0,%1,%2,%3}, [%4];"
        : "=r"(r[0]), "=r"(r[1]), "=r"(r[2]), "=r"(r[3]) : "r"(addr));
}
// fp16 mma: m16n8k16, fp32 accumulate
__device__ __forceinline__ void mma16816(float* d, const uint32_t* a, const uint32_t* b) {
    asm volatile("mma.sync.aligned.m16n8k16.row.col.f32.f16.f16.f32 "
        "{%0,%1,%2,%3}, {%4,%5,%6,%7}, {%8,%9}, {%0,%1,%2,%3};"
        : "+f"(d[0]), "+f"(d[1]), "+f"(d[2]), "+f"(d[3])
        : "r"(a[0]), "r"(a[1]), "r"(a[2]), "r"(a[3]), "r"(b[0]), "r"(b[1]));
}
// pack two floats as half2 word
__device__ __forceinline__ uint32_t packh2(float x, float y) {
    __half2 h = __floats2half2_rn(x, y);
    uint32_t u; memcpy(&u, &h, 4); return u;
}

// ---------------- K1: voxel index + scatter-mean accumulators ----------------
__global__ void k_scatter(const float4* __restrict__ feats, const int4* __restrict__ coors)
{
    int p = blockIdx.x * 256 + threadIdx.x;
    if (p >= NPTS) return;
    int4 c = coors[p];
    int idx = ((c.x + c.y) * NYG + c.z) * NXG + c.w;
    g_idx[p] = idx;
    float4 f = feats[p];
    atomicAdd(&g_vsum[idx * 3 + 0], f.x);
    atomicAdd(&g_vsum[idx * 3 + 1], f.y);
    atomicAdd(&g_vsum[idx * 3 + 2], f.z);
    atomicAdd(&g_vcnt[idx], 1.0f);
}

// ---------------- K2: 10-d feature, z0 = feat @ W0, fused BN0 stats + coalesced raw voxel max ----------------
__global__ void k_feat0(const float4* __restrict__ feats, const int4* __restrict__ coors,
                        const float* __restrict__ W0)
{
    __shared__ float Ws[640];
    __shared__ float outS[128 * 65];
    __shared__ int   sIdxS[128];
    int t  = threadIdx.x;
    int p0 = blockIdx.x * 128;
    for (int i = t; i < 640; i += 128) Ws[i] = W0[i];

    int p = p0 + t;
    int4  c = coors[p];
    float4 f = feats[p];
    int   idx = g_idx[p];
    sIdxS[t] = idx;
    float inv = 1.0f / g_vcnt[idx];
    float mx = g_vsum[idx * 3 + 0] * inv;
    float my = g_vsum[idx * 3 + 1] * inv;
    float mz = g_vsum[idx * 3 + 2] * inv;

    float f10[10];
    f10[0] = f.x;  f10[1] = f.y;  f10[2] = f.z;  f10[3] = f.w;
    f10[4] = f.x - mx;  f10[5] = f.y - my;  f10[6] = f.z - mz;
    f10[7] = f.x - ((float)c.w * 0.2f + 0.1f);
    f10[8] = f.y - ((float)c.z * 0.2f - 39.9f);
    f10[9] = f.z - ((float)c.y * 4.0f - 1.0f);
    __syncthreads();

    #pragma unroll
    for (int j = 0; j < 64; j++) {
        float acc = 0.f;
        #pragma unroll
        for (int k = 0; k < 10; k++) acc = fmaf(f10[k], Ws[k * 64 + j], acc);
        outS[t * 65 + j] = acc;
    }
    __syncthreads();

    // coalesced z0 store
    float4* gout = (float4*)(g_z0 + (size_t)p0 * 64);
    #pragma unroll
    for (int it = 0; it < 16; it++) {
        int gid = t + it * 128;
        int row = gid >> 4;
        int col = (gid & 15) << 2;
        const float* s = &outS[row * 65 + col];
        gout[gid] = make_float4(s[0], s[1], s[2], s[3]);
    }

    // coalesced scatter-max of RAW z0 into encoded canvas (warp = 2 points x 16 slots)
    #pragma unroll
    for (int it = 0; it < 16; it++) {
        int slot = t + it * 128;
        int pl = slot >> 4;
        int c4 = (slot & 15) << 2;
        const float* s = &outS[pl * 65 + c4];
        uint32_t* dst = g_enc0 + ((size_t)sIdxS[pl] << 6) + c4;
        atomicMax(dst + 0, encf(s[0]));
        atomicMax(dst + 1, encf(s[1]));
        atomicMax(dst + 2, encf(s[2]));
        atomicMax(dst + 3, encf(s[3]));
    }

    // fused BN0 stats: thread t sums 64 rows of channel (t & 63)
    {
        int ch = t & 63;
        int r0 = (t >> 6) * 64;
        float s = 0.f, q = 0.f;
        #pragma unroll 8
        for (int r = 0; r < 64; r++) {
            float v = outS[(r0 + r) * 65 + ch];
            s += v;
            q = fmaf(v, v, q);
        }
        atomicAdd(&g_stats[ch], (double)s);
        atomicAdd(&g_stats[64 + ch], (double)q);
    }
}

// ---------------- K4/K8: fold BN stats + affine into a*x + c ----------------
__global__ void k_bnfin(const float* __restrict__ gamma, const float* __restrict__ beta,
                        int nch, int s_off, int ab_off)
{
    int c = threadIdx.x;
    if (c >= nch) return;
    double mu  = g_stats[s_off + c] * (1.0 / NPTS);
    double var = g_stats[s_off + nch + c] * (1.0 / NPTS) - mu * mu;
    float rstd = rsqrtf((float)var + BNEPS);
    float a = gamma[c] * rstd;
    g_ab[ab_off + c]       = a;
    g_ab[ab_off + nch + c] = beta[c] - (float)mu * a;
}

// ---------------- K6: fp16 2-term mma.sync GEMM ----------------
// z1 = feat1 @ W1 with W1^T split exactly into fp16 hi+lo (A operand, register-
// resident); feat1 = [relu(bn0(z0)) | relu(bn0(dec(enc0[idx])))] rounded to ONE
// fp16 plane (B operand). 2 mma terms per k-step instead of 3 — the mma.sync
// instruction rate (~19 cyc/SMSP, schedule-invariant across R9/R10/R11) is the
// binding resource, so count is the only lever. Error: fp16 rounding of feat
// ~2.8e-4 RMS, under the 1e-3 gate.
#define ROWB    272
#define PLANE   (128 * ROWB)        // 34816
#define FBASE   (2 * PLANE)         // single feat plane after W hi/lo planes
#define GSMEM   (3 * PLANE)         // 104448

__global__ void __launch_bounds__(256, 1) k_gemm_mma(const float* __restrict__ W1)
{
    extern __shared__ char sm[];
    uint32_t sbase = smem_u32(sm);
    int t = threadIdx.x, w = t >> 5, lane = t & 31;
    int n0 = w * 16;

    // one-time: W1^T hi/lo fp16 planes (row n, col k); hi+lo is exact
    for (int i = t; i < 16384; i += 256) {
        int k = i >> 7, n = i & 127;
        float v = W1[i];
        __half h = __float2half_rn(v);
        __half l = __float2half_rn(v - __half2float(h));
        *(__half*)(sm + n * ROWB + 2 * k) = h;
        *(__half*)(sm + PLANE + n * ROWB + 2 * k) = l;
    }
    __syncthreads();

    // weight fragments: registers, persistent across tiles
    uint32_t Ah[8][4], Al[8][4];
    {
        int g = lane >> 3, r8 = lane & 7;
        uint32_t row = (uint32_t)(n0 + (g & 1) * 8 + r8) * ROWB + (uint32_t)((g >> 1) * 16);
        #pragma unroll
        for (int ks = 0; ks < 8; ks++) {
            ldsm_x4(Ah[ks], sbase + row + ks * 32);
            ldsm_x4(Al[ks], sbase + PLANE + row + ks * 32);
        }
    }

    float ba0 = g_ab[2 * lane],     bc0 = g_ab[64 + 2 * lane];
    float ba1 = g_ab[2 * lane + 1], bc1 = g_ab[64 + 2 * lane + 1];

    float s1 = 0.f, q1 = 0.f, s2 = 0.f, q2 = 0.f;

    // ldmatrix.x4 feat addressing: mats 0,1 = mb rows (k halves), mats 2,3 = mb+1 rows
    uint32_t baddr4 = sbase + FBASE
                    + (uint32_t)((lane & 7) * ROWB + ((lane >> 3) & 1) * 16
                               + (lane >> 4) * 8 * ROWB);

    for (int tile = blockIdx.x; tile < NTILES; tile += gridDim.x) {
        int m0 = tile * 128;
        __syncthreads();                          // prev tile's ldsm reads done

        // build single fp16 feat plane with direct LDG: warp w rows [w*16, w*16+16)
        {
            float2   zv[16];
            uint2    gv[16];
            int      idxr[16];
            #pragma unroll
            for (int rr = 0; rr < 16; rr++) {
                int gm = m0 + w * 16 + rr;
                idxr[rr] = g_idx[gm];             // warp-broadcast load
                zv[rr] = *(const float2*)(g_z0 + ((size_t)gm << 6) + 2 * lane);
            }
            #pragma unroll
            for (int rr = 0; rr < 16; rr++)
                gv[rr] = *(const uint2*)(g_enc0 + ((size_t)idxr[rr] << 6) + 2 * lane);
            #pragma unroll
            for (int rr = 0; rr < 16; rr++) {
                int r = w * 16 + rr;
                float p0 = fmaxf(fmaf(zv[rr].x, ba0, bc0), 0.f);
                float p1 = fmaxf(fmaf(zv[rr].y, ba1, bc1), 0.f);
                char* rp = sm + FBASE + r * ROWB + 4 * lane;
                *(uint32_t*)(rp) = packh2(p0, p1);
                float g0f = fmaxf(fmaf(decf(gv[rr].x), ba0, bc0), 0.f);  // occupied only
                float g1f = fmaxf(fmaf(decf(gv[rr].y), ba1, bc1), 0.f);
                *(uint32_t*)(rp + 128) = packh2(g0f, g1f);
            }
        }
        __syncthreads();

        // 4 mb-blocks per iteration: 4 independent accumulator chains, 2 terms each
        #pragma unroll
        for (int mb = 0; mb < 16; mb += 4) {
            float a0[4] = {0,0,0,0}, a1[4] = {0,0,0,0};
            float a2[4] = {0,0,0,0}, a3[4] = {0,0,0,0};
            uint32_t ab01 = baddr4 + (uint32_t)(mb * 8 * ROWB);
            uint32_t ab23 = ab01 + 16 * ROWB;
            #pragma unroll
            for (int ks = 0; ks < 8; ks++) {
                uint32_t B01[4], B23[4];
                ldsm_x4(B01, ab01 + ks * 32);
                ldsm_x4(B23, ab23 + ks * 32);
                mma16816(a0, Ah[ks], B01);      mma16816(a1, Ah[ks], B01 + 2);
                mma16816(a2, Ah[ks], B23);      mma16816(a3, Ah[ks], B23 + 2);
                mma16816(a0, Al[ks], B01);      mma16816(a1, Al[ks], B01 + 2);
                mma16816(a2, Al[ks], B23);      mma16816(a3, Al[ks], B23 + 2);
            }
            // epilogue: z1 stores + BN1 stats
            int c = n0 + (lane >> 2);
            int mbase = m0 + (lane & 3) * 2;
            float* rowp;
            #define EPI(J, ACC)                                                     \
                rowp = g_z1 + (size_t)(mbase + (mb + J) * 8) * 128 + c;             \
                rowp[0]   = ACC[0];  rowp[128] = ACC[1];                            \
                rowp[8]   = ACC[2];  rowp[136] = ACC[3];                            \
                s1 += ACC[0] + ACC[1];  q1 += ACC[0]*ACC[0] + ACC[1]*ACC[1];        \
                s2 += ACC[2] + ACC[3];  q2 += ACC[2]*ACC[2] + ACC[3]*ACC[3];
            EPI(0, a0)  EPI(1, a1)  EPI(2, a2)  EPI(3, a3)
            #undef EPI
        }
    }

    // fused layer-1 BN stats: reduce over the 4 lanes sharing each channel
    #pragma unroll
    for (int off = 1; off <= 2; off <<= 1) {
        s1 += __shfl_xor_sync(0xffffffffu, s1, off);
        q1 += __shfl_xor_sync(0xffffffffu, q1, off);
        s2 += __shfl_xor_sync(0xffffffffu, s2, off);
        q2 += __shfl_xor_sync(0xffffffffu, q2, off);
    }
    if ((lane & 3) == 0) {
        int c = n0 + (lane >> 2);
        atomicAdd(&g_stats[128 + c],     (double)s1);
        atomicAdd(&g_stats[256 + c],     (double)q1);
        atomicAdd(&g_stats[128 + c + 8], (double)s2);
        atomicAdd(&g_stats[256 + c + 8], (double)q2);
    }
}

// ---------------- K9: pf1 = relu(a*z1+c), scatter-max into dense output (float4) ----------------
__global__ void k_relumax1(float* __restrict__ out)
{
    int tid = blockIdx.x * 256 + threadIdx.x;     // NPTS*32 threads
    int c4 = (tid & 31) << 2;
    int p  = tid >> 5;
    float4 z = *(const float4*)(g_z1 + ((size_t)p << 7) + c4);
    float4 a = *(const float4*)(g_ab + 128 + c4);
    float4 b = *(const float4*)(g_ab + 256 + c4);
    float v0 = fmaxf(fmaf(z.x, a.x, b.x), 0.f);
    float v1 = fmaxf(fmaf(z.y, a.y, b.y), 0.f);
    float v2 = fmaxf(fmaf(z.z, a.z, b.z), 0.f);
    float v3 = fmaxf(fmaf(z.w, a.w, b.w), 0.f);
    unsigned int* dst = (unsigned int*)(out + ((size_t)g_idx[p] << 7) + c4);
    if (v0 > 0.f) atomicMax(dst + 0, __float_as_uint(v0));
    if (v1 > 0.f) atomicMax(dst + 1, __float_as_uint(v1));
    if (v2 > 0.f) atomicMax(dst + 2, __float_as_uint(v2));
    if (v3 > 0.f) atomicMax(dst + 3, __float_as_uint(v3));
}

// ---------------- launch ----------------
extern "C" void kernel_launch(void* const* d_in, const int* in_sizes, int n_in,
                              void* d_out, int out_size)
{
    const float* feats = (const float*)d_in[0];
    const int*   coors = (const int*)d_in[1];
    const float* W0 = (const float*)d_in[2];
    const float* g0 = (const float*)d_in[3];
    const float* b0 = (const float*)d_in[4];
    const float* W1 = (const float*)d_in[5];
    const float* g1 = (const float*)d_in[6];
    const float* b1 = (const float*)d_in[7];
    (void)in_sizes; (void)n_in;

    void *p_vsum, *p_vcnt, *p_enc0, *p_stats;
    cudaGetSymbolAddress(&p_vsum,  g_vsum);
    cudaGetSymbolAddress(&p_vcnt,  g_vcnt);
    cudaGetSymbolAddress(&p_enc0,  g_enc0);
    cudaGetSymbolAddress(&p_stats, g_stats);

    cudaMemsetAsync(p_vsum,  0, sizeof(float) * CANVAS * 3, 0);
    cudaMemsetAsync(p_vcnt,  0, sizeof(float) * CANVAS, 0);
    cudaMemsetAsync(p_enc0,  0, sizeof(uint32_t) * (size_t)CANVAS * 64, 0);
    cudaMemsetAsync(p_stats, 0, sizeof(double) * 512, 0);
    cudaMemsetAsync(d_out,   0, sizeof(float) * (size_t)out_size, 0);

    k_scatter<<<(NPTS + 255) / 256, 256>>>((const float4*)feats, (const int4*)coors);
    k_feat0<<<NPTS / 128, 128>>>((const float4*)feats, (const int4*)coors, W0);
    k_bnfin<<<1, 128>>>(g0, b0, 64, 0, 0);

    cudaFuncSetAttribute(k_gemm_mma, cudaFuncAttributeMaxDynamicSharedMemorySize, GSMEM);
    k_gemm_mma<<<148, 256, GSMEM>>>(W1);    // also accumulates layer-1 BN stats

    k_bnfin<<<1, 128>>>(g1, b1, 128, 128, 128);
    k_relumax1<<<(NPTS * 32) / 256, 256>>>((float*)d_out);
}

// round 14
// speedup vs baseline: 1.3961x; 1.3961x over previous
#include <cuda_runtime.h>
#include <cuda_fp16.h>
#include <cstdint>
#include <cstring>

#define NPTS   400000
#define NXG    352
#define NYG    400
#define CANVAS 281600          // 2 * 1 * 400 * 352
#define BNEPS  1e-3f
#define NTILES (NPTS / 128)    // 3125

// ---------------- scratch (static __device__ — no allocation allowed) ----------------
static __device__ int      g_idx[NPTS];
static __device__ float    g_vsum[CANVAS * 3];
static __device__ float    g_vcnt[CANVAS];
static __device__ float    g_z0[(size_t)NPTS * 64];      // raw z0 (pre-BN)
static __device__ uint32_t g_enc0[(size_t)CANVAS * 64];  // enc(max raw z0) per voxel
static __device__ float    g_z1[(size_t)NPTS * 128];
static __device__ double   g_stats[512];                 // s0 q0 s1 q1
static __device__ float    g_ab[384];                    // a0 c0 a1 c1 (folded BN)

// ================= helpers =================
__device__ __forceinline__ uint32_t smem_u32(const void* p) {
    uint32_t a;
    asm("{ .reg .u64 t; cvta.to.shared.u64 t, %1; cvt.u32.u64 %0, t; }" : "=r"(a) : "l"(p));
    return a;
}
// monotone float <-> uint (total order); enc(x) == 0 only for untouched sentinel
__device__ __forceinline__ uint32_t encf(float x) {
    uint32_t b = __float_as_uint(x);
    return (b & 0x80000000u) ? ~b : (b | 0x80000000u);
}
__device__ __forceinline__ float decf(uint32_t u) {
    return __uint_as_float((u & 0x80000000u) ? (u & 0x7FFFFFFFu) : ~u);
}
__device__ __forceinline__ void ldsm_x4(uint32_t* r, uint32_t addr) {
    asm volatile("ldmatrix.sync.aligned.m8n8.x4.shared.b16 {%0,%1,%2,%3}, [%4];"
        : "=r"(r[0]), "=r"(r[1]), "=r"(r[2]), "=r"(r[3]) : "r"(addr));
}
// fp16 mma: m16n8k16, fp32 accumulate
__device__ __forceinline__ void mma16816(float* d, const uint32_t* a, const uint32_t* b) {
    asm volatile("mma.sync.aligned.m16n8k16.row.col.f32.f16.f16.f32 "
        "{%0,%1,%2,%3}, {%4,%5,%6,%7}, {%8,%9}, {%0,%1,%2,%3};"
        : "+f"(d[0]), "+f"(d[1]), "+f"(d[2]), "+f"(d[3])
        : "r"(a[0]), "r"(a[1]), "r"(a[2]), "r"(a[3]), "r"(b[0]), "r"(b[1]));
}
// pack two floats as half2 word
__device__ __forceinline__ uint32_t packh2(float x, float y) {
    __half2 h = __floats2half2_rn(x, y);
    uint32_t u; memcpy(&u, &h, 4); return u;
}

// ---------------- K1: voxel index + scatter-mean accumulators ----------------
__global__ void k_scatter(const float4* __restrict__ feats, const int4* __restrict__ coors)
{
    int p = blockIdx.x * 256 + threadIdx.x;
    if (p >= NPTS) return;
    int4 c = coors[p];
    int idx = ((c.x + c.y) * NYG + c.z) * NXG + c.w;
    g_idx[p] = idx;
    float4 f = feats[p];
    atomicAdd(&g_vsum[idx * 3 + 0], f.x);
    atomicAdd(&g_vsum[idx * 3 + 1], f.y);
    atomicAdd(&g_vsum[idx * 3 + 2], f.z);
    atomicAdd(&g_vcnt[idx], 1.0f);
}

// ---------------- K2: 10-d feature, z0 = feat @ W0, fused BN0 stats + coalesced raw voxel max ----------------
__global__ void k_feat0(const float4* __restrict__ feats, const int4* __restrict__ coors,
                        const float* __restrict__ W0)
{
    __shared__ float Ws[640];
    __shared__ float outS[128 * 65];
    __shared__ int   sIdxS[128];
    int t  = threadIdx.x;
    int p0 = blockIdx.x * 128;
    for (int i = t; i < 640; i += 128) Ws[i] = W0[i];

    int p = p0 + t;
    int4  c = coors[p];
    float4 f = feats[p];
    int   idx = g_idx[p];
    sIdxS[t] = idx;
    float inv = 1.0f / g_vcnt[idx];
    float mx = g_vsum[idx * 3 + 0] * inv;
    float my = g_vsum[idx * 3 + 1] * inv;
    float mz = g_vsum[idx * 3 + 2] * inv;

    float f10[10];
    f10[0] = f.x;  f10[1] = f.y;  f10[2] = f.z;  f10[3] = f.w;
    f10[4] = f.x - mx;  f10[5] = f.y - my;  f10[6] = f.z - mz;
    f10[7] = f.x - ((float)c.w * 0.2f + 0.1f);
    f10[8] = f.y - ((float)c.z * 0.2f - 39.9f);
    f10[9] = f.z - ((float)c.y * 4.0f - 1.0f);
    __syncthreads();

    #pragma unroll
    for (int j = 0; j < 64; j++) {
        float acc = 0.f;
        #pragma unroll
        for (int k = 0; k < 10; k++) acc = fmaf(f10[k], Ws[k * 64 + j], acc);
        outS[t * 65 + j] = acc;
    }
    __syncthreads();

    // coalesced z0 store
    float4* gout = (float4*)(g_z0 + (size_t)p0 * 64);
    #pragma unroll
    for (int it = 0; it < 16; it++) {
        int gid = t + it * 128;
        int row = gid >> 4;
        int col = (gid & 15) << 2;
        const float* s = &outS[row * 65 + col];
        gout[gid] = make_float4(s[0], s[1], s[2], s[3]);
    }

    // coalesced scatter-max of RAW z0 into encoded canvas (warp = 2 points x 16 slots)
    #pragma unroll
    for (int it = 0; it < 16; it++) {
        int slot = t + it * 128;
        int pl = slot >> 4;
        int c4 = (slot & 15) << 2;
        const float* s = &outS[pl * 65 + c4];
        uint32_t* dst = g_enc0 + ((size_t)sIdxS[pl] << 6) + c4;
        atomicMax(dst + 0, encf(s[0]));
        atomicMax(dst + 1, encf(s[1]));
        atomicMax(dst + 2, encf(s[2]));
        atomicMax(dst + 3, encf(s[3]));
    }

    // fused BN0 stats: thread t sums 64 rows of channel (t & 63)
    {
        int ch = t & 63;
        int r0 = (t >> 6) * 64;
        float s = 0.f, q = 0.f;
        #pragma unroll 8
        for (int r = 0; r < 64; r++) {
            float v = outS[(r0 + r) * 65 + ch];
            s += v;
            q = fmaf(v, v, q);
        }
        atomicAdd(&g_stats[ch], (double)s);
        atomicAdd(&g_stats[64 + ch], (double)q);
    }
}

// ---------------- K4/K8: fold BN stats + affine into a*x + c ----------------
__global__ void k_bnfin(const float* __restrict__ gamma, const float* __restrict__ beta,
                        int nch, int s_off, int ab_off)
{
    int c = threadIdx.x;
    if (c >= nch) return;
    double mu  = g_stats[s_off + c] * (1.0 / NPTS);
    double var = g_stats[s_off + nch + c] * (1.0 / NPTS) - mu * mu;
    float rstd = rsqrtf((float)var + BNEPS);
    float a = gamma[c] * rstd;
    g_ab[ab_off + c]       = a;
    g_ab[ab_off + nch + c] = beta[c] - (float)mu * a;
}

// ---------------- K6: fp16 2-term mma.sync GEMM, 2 CTAs/SM ----------------
// z1 = feat1 @ W1; W1^T split exactly into fp16 hi+lo (register-resident A);
// feat1 in ONE fp16 plane (B). Smem 102KB/CTA -> 2 CTAs/SM (4 warps/SMSP),
// attacking the measured issue/occupancy plateau (occ 12.5%, ~20cyc/mma slot,
// schedule-invariant across R7-R11). launch_bounds(256,2) caps regs at 128:
// 2 accumulator chains, build staged in 8-row chunks.
#define ROWB    272
#define PLANE   (128 * ROWB)        // 34816
#define FBASE   (2 * PLANE)         // single feat plane after W hi/lo planes
#define GSMEM   (3 * PLANE)         // 104448 (x2 CTAs = 204KB/SM, fits 228KB)
#define GGRID   296                 // 2 per SM

__global__ void __launch_bounds__(256, 2) k_gemm_mma(const float* __restrict__ W1)
{
    extern __shared__ char sm[];
    uint32_t sbase = smem_u32(sm);
    int t = threadIdx.x, w = t >> 5, lane = t & 31;
    int n0 = w * 16;

    // one-time: W1^T hi/lo fp16 planes (row n, col k); hi+lo is exact
    for (int i = t; i < 16384; i += 256) {
        int k = i >> 7, n = i & 127;
        float v = W1[i];
        __half h = __float2half_rn(v);
        __half l = __float2half_rn(v - __half2float(h));
        *(__half*)(sm + n * ROWB + 2 * k) = h;
        *(__half*)(sm + PLANE + n * ROWB + 2 * k) = l;
    }
    __syncthreads();

    // weight fragments: registers, persistent across tiles (64 regs)
    uint32_t Ah[8][4], Al[8][4];
    {
        int g = lane >> 3, r8 = lane & 7;
        uint32_t row = (uint32_t)(n0 + (g & 1) * 8 + r8) * ROWB + (uint32_t)((g >> 1) * 16);
        #pragma unroll
        for (int ks = 0; ks < 8; ks++) {
            ldsm_x4(Ah[ks], sbase + row + ks * 32);
            ldsm_x4(Al[ks], sbase + PLANE + row + ks * 32);
        }
    }

    float ba0 = g_ab[2 * lane],     bc0 = g_ab[64 + 2 * lane];
    float ba1 = g_ab[2 * lane + 1], bc1 = g_ab[64 + 2 * lane + 1];

    float s1 = 0.f, q1 = 0.f, s2 = 0.f, q2 = 0.f;

    // ldmatrix.x4 feat addressing: mats 0,1 = mb rows (k halves), mats 2,3 = mb+1 rows
    uint32_t baddr4 = sbase + FBASE
                    + (uint32_t)((lane & 7) * ROWB + ((lane >> 3) & 1) * 16
                               + (lane >> 4) * 8 * ROWB);

    for (int tile = blockIdx.x; tile < NTILES; tile += gridDim.x) {
        int m0 = tile * 128;
        __syncthreads();                          // prev tile's ldsm reads done

        // build single fp16 feat plane, direct LDG, staged in 8-row chunks (reg cap)
        #pragma unroll
        for (int half = 0; half < 2; half++) {
            float2   zv[8];
            uint2    gv[8];
            int      idxr[8];
            #pragma unroll
            for (int rr = 0; rr < 8; rr++) {
                int gm = m0 + w * 16 + half * 8 + rr;
                idxr[rr] = g_idx[gm];             // warp-broadcast load
                zv[rr] = *(const float2*)(g_z0 + ((size_t)gm << 6) + 2 * lane);
            }
            #pragma unroll
            for (int rr = 0; rr < 8; rr++)
                gv[rr] = *(const uint2*)(g_enc0 + ((size_t)idxr[rr] << 6) + 2 * lane);
            #pragma unroll
            for (int rr = 0; rr < 8; rr++) {
                int r = w * 16 + half * 8 + rr;
                float p0 = fmaxf(fmaf(zv[rr].x, ba0, bc0), 0.f);
                float p1 = fmaxf(fmaf(zv[rr].y, ba1, bc1), 0.f);
                char* rp = sm + FBASE + r * ROWB + 4 * lane;
                *(uint32_t*)(rp) = packh2(p0, p1);
                float g0f = fmaxf(fmaf(decf(gv[rr].x), ba0, bc0), 0.f);  // occupied only
                float g1f = fmaxf(fmaf(decf(gv[rr].y), ba1, bc1), 0.f);
                *(uint32_t*)(rp + 128) = packh2(g0f, g1f);
            }
        }
        __syncthreads();

        // 2 mb-blocks per iteration: 2 independent accumulator chains, 2 terms each
        #pragma unroll
        for (int mb = 0; mb < 16; mb += 2) {
            float a0[4] = {0,0,0,0}, a1[4] = {0,0,0,0};
            uint32_t ab = baddr4 + (uint32_t)(mb * 8 * ROWB);
            #pragma unroll
            for (int ks = 0; ks < 8; ks++) {
                uint32_t B[4];
                ldsm_x4(B, ab + ks * 32);
                mma16816(a0, Ah[ks], B);        mma16816(a1, Ah[ks], B + 2);
                mma16816(a0, Al[ks], B);        mma16816(a1, Al[ks], B + 2);
            }
            // epilogue: z1 stores + BN1 stats
            int c = n0 + (lane >> 2);
            int mbase = m0 + (lane & 3) * 2;
            float* rowp;
            #define EPI(J, ACC)                                                     \
                rowp = g_z1 + (size_t)(mbase + (mb + J) * 8) * 128 + c;             \
                rowp[0]   = ACC[0];  rowp[128] = ACC[1];                            \
                rowp[8]   = ACC[2];  rowp[136] = ACC[3];                            \
                s1 += ACC[0] + ACC[1];  q1 += ACC[0]*ACC[0] + ACC[1]*ACC[1];        \
                s2 += ACC[2] + ACC[3];  q2 += ACC[2]*ACC[2] + ACC[3]*ACC[3];
            EPI(0, a0)  EPI(1, a1)
            #undef EPI
        }
    }

    // fused layer-1 BN stats: reduce over the 4 lanes sharing each channel
    #pragma unroll
    for (int off = 1; off <= 2; off <<= 1) {
        s1 += __shfl_xor_sync(0xffffffffu, s1, off);
        q1 += __shfl_xor_sync(0xffffffffu, q1, off);
        s2 += __shfl_xor_sync(0xffffffffu, s2, off);
        q2 += __shfl_xor_sync(0xffffffffu, q2, off);
    }
    if ((lane & 3) == 0) {
        int c = n0 + (lane >> 2);
        atomicAdd(&g_stats[128 + c],     (double)s1);
        atomicAdd(&g_stats[256 + c],     (double)q1);
        atomicAdd(&g_stats[128 + c + 8], (double)s2);
        atomicAdd(&g_stats[256 + c + 8], (double)q2);
    }
}

// ---------------- K9: pf1 = relu(a*z1+c), scatter-max into dense output (float4) ----------------
__global__ void k_relumax1(float* __restrict__ out)
{
    int tid = blockIdx.x * 256 + threadIdx.x;     // NPTS*32 threads
    int c4 = (tid & 31) << 2;
    int p  = tid >> 5;
    float4 z = *(const float4*)(g_z1 + ((size_t)p << 7) + c4);
    float4 a = *(const float4*)(g_ab + 128 + c4);
    float4 b = *(const float4*)(g_ab + 256 + c4);
    float v0 = fmaxf(fmaf(z.x, a.x, b.x), 0.f);
    float v1 = fmaxf(fmaf(z.y, a.y, b.y), 0.f);
    float v2 = fmaxf(fmaf(z.z, a.z, b.z), 0.f);
    float v3 = fmaxf(fmaf(z.w, a.w, b.w), 0.f);
    unsigned int* dst = (unsigned int*)(out + ((size_t)g_idx[p] << 7) + c4);
    if (v0 > 0.f) atomicMax(dst + 0, __float_as_uint(v0));
    if (v1 > 0.f) atomicMax(dst + 1, __float_as_uint(v1));
    if (v2 > 0.f) atomicMax(dst + 2, __float_as_uint(v2));
    if (v3 > 0.f) atomicMax(dst + 3, __float_as_uint(v3));
}

// ---------------- launch ----------------
extern "C" void kernel_launch(void* const* d_in, const int* in_sizes, int n_in,
                              void* d_out, int out_size)
{
    const float* feats = (const float*)d_in[0];
    const int*   coors = (const int*)d_in[1];
    const float* W0 = (const float*)d_in[2];
    const float* g0 = (const float*)d_in[3];
    const float* b0 = (const float*)d_in[4];
    const float* W1 = (const float*)d_in[5];
    const float* g1 = (const float*)d_in[6];
    const float* b1 = (const float*)d_in[7];
    (void)in_sizes; (void)n_in;

    void *p_vsum, *p_vcnt, *p_enc0, *p_stats;
    cudaGetSymbolAddress(&p_vsum,  g_vsum);
    cudaGetSymbolAddress(&p_vcnt,  g_vcnt);
    cudaGetSymbolAddress(&p_enc0,  g_enc0);
    cudaGetSymbolAddress(&p_stats, g_stats);

    cudaMemsetAsync(p_vsum,  0, sizeof(float) * CANVAS * 3, 0);
    cudaMemsetAsync(p_vcnt,  0, sizeof(float) * CANVAS, 0);
    cudaMemsetAsync(p_enc0,  0, sizeof(uint32_t) * (size_t)CANVAS * 64, 0);
    cudaMemsetAsync(p_stats, 0, sizeof(double) * 512, 0);
    cudaMemsetAsync(d_out,   0, sizeof(float) * (size_t)out_size, 0);

    k_scatter<<<(NPTS + 255) / 256, 256>>>((const float4*)feats, (const int4*)coors);
    k_feat0<<<NPTS / 128, 128>>>((const float4*)feats, (const int4*)coors, W0);
    k_bnfin<<<1, 128>>>(g0, b0, 64, 0, 0);

    cudaFuncSetAttribute(k_gemm_mma, cudaFuncAttributeMaxDynamicSharedMemorySize, GSMEM);
    k_gemm_mma<<<GGRID, 256, GSMEM>>>(W1);    // 2 CTAs/SM; also BN1 stats

    k_bnfin<<<1, 128>>>(g1, b1, 128, 128, 128);
    k_relumax1<<<(NPTS * 32) / 256, 256>>>((float*)d_out);
}

// round 15
// speedup vs baseline: 1.5742x; 1.1276x over previous
#include <cuda_runtime.h>
#include <cuda_fp16.h>
#include <cstdint>
#include <cstring>

#define NPTS   400000
#define NXG    352
#define NYG    400
#define CANVAS 281600          // 2 * 1 * 400 * 352
#define BNEPS  1e-3f
#define NTILES (NPTS / 128)    // 3125

// ---------------- scratch (static __device__ — no allocation allowed) ----------------
static __device__ int      g_idx[NPTS];
static __device__ float    g_vsum[CANVAS * 3];
static __device__ float    g_vcnt[CANVAS];
static __device__ float    g_z0[(size_t)NPTS * 64];      // raw z0 (pre-BN)
static __device__ uint32_t g_enc0[(size_t)CANVAS * 64];  // enc(max raw z0) per voxel
static __device__ uint32_t g_z1h[(size_t)NPTS * 64];     // z1 as half2: word cw = ch (cw>>3)*16+(cw&7), +8
static __device__ double   g_stats[512];                 // s0 q0 s1 q1
static __device__ float    g_ab[384];                    // a0 c0 a1 c1 (folded BN)

// ================= helpers =================
__device__ __forceinline__ uint32_t smem_u32(const void* p) {
    uint32_t a;
    asm("{ .reg .u64 t; cvta.to.shared.u64 t, %1; cvt.u32.u64 %0, t; }" : "=r"(a) : "l"(p));
    return a;
}
// monotone float <-> uint (total order); enc(x) == 0 only for untouched sentinel
__device__ __forceinline__ uint32_t encf(float x) {
    uint32_t b = __float_as_uint(x);
    return (b & 0x80000000u) ? ~b : (b | 0x80000000u);
}
__device__ __forceinline__ float decf(uint32_t u) {
    return __uint_as_float((u & 0x80000000u) ? (u & 0x7FFFFFFFu) : ~u);
}
__device__ __forceinline__ void ldsm_x4(uint32_t* r, uint32_t addr) {
    asm volatile("ldmatrix.sync.aligned.m8n8.x4.shared.b16 {%0,%1,%2,%3}, [%4];"
        : "=r"(r[0]), "=r"(r[1]), "=r"(r[2]), "=r"(r[3]) : "r"(addr));
}
// fp16 mma: m16n8k16, fp32 accumulate
__device__ __forceinline__ void mma16816(float* d, const uint32_t* a, const uint32_t* b) {
    asm volatile("mma.sync.aligned.m16n8k16.row.col.f32.f16.f16.f32 "
        "{%0,%1,%2,%3}, {%4,%5,%6,%7}, {%8,%9}, {%0,%1,%2,%3};"
        : "+f"(d[0]), "+f"(d[1]), "+f"(d[2]), "+f"(d[3])
        : "r"(a[0]), "r"(a[1]), "r"(a[2]), "r"(a[3]), "r"(b[0]), "r"(b[1]));
}
// pack two floats as half2 word
__device__ __forceinline__ uint32_t packh2(float x, float y) {
    __half2 h = __floats2half2_rn(x, y);
    uint32_t u; memcpy(&u, &h, 4); return u;
}
__device__ __forceinline__ void unpackh2(uint32_t u, float& x, float& y) {
    __half2 h; memcpy(&h, &u, 4);
    x = __low2float(h); y = __high2float(h);
}

// ---------------- K1: voxel index + scatter-mean accumulators ----------------
__global__ void k_scatter(const float4* __restrict__ feats, const int4* __restrict__ coors)
{
    int p = blockIdx.x * 256 + threadIdx.x;
    if (p >= NPTS) return;
    int4 c = coors[p];
    int idx = ((c.x + c.y) * NYG + c.z) * NXG + c.w;
    g_idx[p] = idx;
    float4 f = feats[p];
    atomicAdd(&g_vsum[idx * 3 + 0], f.x);
    atomicAdd(&g_vsum[idx * 3 + 1], f.y);
    atomicAdd(&g_vsum[idx * 3 + 2], f.z);
    atomicAdd(&g_vcnt[idx], 1.0f);
}

// ---------------- K2: 10-d feature, z0 = feat @ W0, fused BN0 stats + coalesced raw voxel max ----------------
__global__ void k_feat0(const float4* __restrict__ feats, const int4* __restrict__ coors,
                        const float* __restrict__ W0)
{
    __shared__ float Ws[640];
    __shared__ float outS[128 * 65];
    __shared__ int   sIdxS[128];
    int t  = threadIdx.x;
    int p0 = blockIdx.x * 128;
    for (int i = t; i < 640; i += 128) Ws[i] = W0[i];

    int p = p0 + t;
    int4  c = coors[p];
    float4 f = feats[p];
    int   idx = g_idx[p];
    sIdxS[t] = idx;
    float inv = 1.0f / g_vcnt[idx];
    float mx = g_vsum[idx * 3 + 0] * inv;
    float my = g_vsum[idx * 3 + 1] * inv;
    float mz = g_vsum[idx * 3 + 2] * inv;

    float f10[10];
    f10[0] = f.x;  f10[1] = f.y;  f10[2] = f.z;  f10[3] = f.w;
    f10[4] = f.x - mx;  f10[5] = f.y - my;  f10[6] = f.z - mz;
    f10[7] = f.x - ((float)c.w * 0.2f + 0.1f);
    f10[8] = f.y - ((float)c.z * 0.2f - 39.9f);
    f10[9] = f.z - ((float)c.y * 4.0f - 1.0f);
    __syncthreads();

    #pragma unroll
    for (int j = 0; j < 64; j++) {
        float acc = 0.f;
        #pragma unroll
        for (int k = 0; k < 10; k++) acc = fmaf(f10[k], Ws[k * 64 + j], acc);
        outS[t * 65 + j] = acc;
    }
    __syncthreads();

    // coalesced z0 store
    float4* gout = (float4*)(g_z0 + (size_t)p0 * 64);
    #pragma unroll
    for (int it = 0; it < 16; it++) {
        int gid = t + it * 128;
        int row = gid >> 4;
        int col = (gid & 15) << 2;
        const float* s = &outS[row * 65 + col];
        gout[gid] = make_float4(s[0], s[1], s[2], s[3]);
    }

    // coalesced scatter-max of RAW z0 into encoded canvas (warp = 2 points x 16 slots)
    #pragma unroll
    for (int it = 0; it < 16; it++) {
        int slot = t + it * 128;
        int pl = slot >> 4;
        int c4 = (slot & 15) << 2;
        const float* s = &outS[pl * 65 + c4];
        uint32_t* dst = g_enc0 + ((size_t)sIdxS[pl] << 6) + c4;
        atomicMax(dst + 0, encf(s[0]));
        atomicMax(dst + 1, encf(s[1]));
        atomicMax(dst + 2, encf(s[2]));
        atomicMax(dst + 3, encf(s[3]));
    }

    // fused BN0 stats: thread t sums 64 rows of channel (t & 63)
    {
        int ch = t & 63;
        int r0 = (t >> 6) * 64;
        float s = 0.f, q = 0.f;
        #pragma unroll 8
        for (int r = 0; r < 64; r++) {
            float v = outS[(r0 + r) * 65 + ch];
            s += v;
            q = fmaf(v, v, q);
        }
        atomicAdd(&g_stats[ch], (double)s);
        atomicAdd(&g_stats[64 + ch], (double)q);
    }
}

// ---------------- K4/K8: fold BN stats + affine into a*x + c ----------------
__global__ void k_bnfin(const float* __restrict__ gamma, const float* __restrict__ beta,
                        int nch, int s_off, int ab_off)
{
    int c = threadIdx.x;
    if (c >= nch) return;
    double mu  = g_stats[s_off + c] * (1.0 / NPTS);
    double var = g_stats[s_off + nch + c] * (1.0 / NPTS) - mu * mu;
    float rstd = rsqrtf((float)var + BNEPS);
    float a = gamma[c] * rstd;
    g_ab[ab_off + c]       = a;
    g_ab[ab_off + nch + c] = beta[c] - (float)mu * a;
}

// ---------------- K6: fp16 2-term mma.sync GEMM, 2 CTAs/SM, fp16 z1 output ----------------
// z1 = feat1 @ W1; W1^T split exactly into fp16 hi+lo (register-resident A);
// feat1 in ONE fp16 plane (B). z1 stored as half2 words (channels c, c+8 packed)
// — halves the GEMM store traffic AND relumax1's read traffic (GEMM was 35% DRAM).
#define ROWB    272
#define PLANE   (128 * ROWB)        // 34816
#define FBASE   (2 * PLANE)         // single feat plane after W hi/lo planes
#define GSMEM   (3 * PLANE)         // 104448 (x2 CTAs = 204KB/SM)
#define GGRID   296                 // 2 per SM

__global__ void __launch_bounds__(256, 2) k_gemm_mma(const float* __restrict__ W1)
{
    extern __shared__ char sm[];
    uint32_t sbase = smem_u32(sm);
    int t = threadIdx.x, w = t >> 5, lane = t & 31;
    int n0 = w * 16;

    // one-time: W1^T hi/lo fp16 planes (row n, col k); hi+lo is exact
    for (int i = t; i < 16384; i += 256) {
        int k = i >> 7, n = i & 127;
        float v = W1[i];
        __half h = __float2half_rn(v);
        __half l = __float2half_rn(v - __half2float(h));
        *(__half*)(sm + n * ROWB + 2 * k) = h;
        *(__half*)(sm + PLANE + n * ROWB + 2 * k) = l;
    }
    __syncthreads();

    // weight fragments: registers, persistent across tiles (64 regs)
    uint32_t Ah[8][4], Al[8][4];
    {
        int g = lane >> 3, r8 = lane & 7;
        uint32_t row = (uint32_t)(n0 + (g & 1) * 8 + r8) * ROWB + (uint32_t)((g >> 1) * 16);
        #pragma unroll
        for (int ks = 0; ks < 8; ks++) {
            ldsm_x4(Ah[ks], sbase + row + ks * 32);
            ldsm_x4(Al[ks], sbase + PLANE + row + ks * 32);
        }
    }

    float ba0 = g_ab[2 * lane],     bc0 = g_ab[64 + 2 * lane];
    float ba1 = g_ab[2 * lane + 1], bc1 = g_ab[64 + 2 * lane + 1];

    float s1 = 0.f, q1 = 0.f, s2 = 0.f, q2 = 0.f;

    // ldmatrix.x4 feat addressing: mats 0,1 = mb rows (k halves), mats 2,3 = mb+1 rows
    uint32_t baddr4 = sbase + FBASE
                    + (uint32_t)((lane & 7) * ROWB + ((lane >> 3) & 1) * 16
                               + (lane >> 4) * 8 * ROWB);

    for (int tile = blockIdx.x; tile < NTILES; tile += gridDim.x) {
        int m0 = tile * 128;
        __syncthreads();                          // prev tile's ldsm reads done

        // build single fp16 feat plane, direct LDG, staged in 8-row chunks (reg cap)
        #pragma unroll
        for (int half = 0; half < 2; half++) {
            float2   zv[8];
            uint2    gv[8];
            int      idxr[8];
            #pragma unroll
            for (int rr = 0; rr < 8; rr++) {
                int gm = m0 + w * 16 + half * 8 + rr;
                idxr[rr] = g_idx[gm];             // warp-broadcast load
                zv[rr] = *(const float2*)(g_z0 + ((size_t)gm << 6) + 2 * lane);
            }
            #pragma unroll
            for (int rr = 0; rr < 8; rr++)
                gv[rr] = *(const uint2*)(g_enc0 + ((size_t)idxr[rr] << 6) + 2 * lane);
            #pragma unroll
            for (int rr = 0; rr < 8; rr++) {
                int r = w * 16 + half * 8 + rr;
                float p0 = fmaxf(fmaf(zv[rr].x, ba0, bc0), 0.f);
                float p1 = fmaxf(fmaf(zv[rr].y, ba1, bc1), 0.f);
                char* rp = sm + FBASE + r * ROWB + 4 * lane;
                *(uint32_t*)(rp) = packh2(p0, p1);
                float g0f = fmaxf(fmaf(decf(gv[rr].x), ba0, bc0), 0.f);  // occupied only
                float g1f = fmaxf(fmaf(decf(gv[rr].y), ba1, bc1), 0.f);
                *(uint32_t*)(rp + 128) = packh2(g0f, g1f);
            }
        }
        __syncthreads();

        // 2 mb-blocks per iteration: 2 independent accumulator chains, 2 terms each
        int cw = w * 8 + (lane >> 2);             // z1h word index (channels c, c+8)
        #pragma unroll
        for (int mb = 0; mb < 16; mb += 2) {
            float a0[4] = {0,0,0,0}, a1[4] = {0,0,0,0};
            uint32_t ab = baddr4 + (uint32_t)(mb * 8 * ROWB);
            #pragma unroll
            for (int ks = 0; ks < 8; ks++) {
                uint32_t B[4];
                ldsm_x4(B, ab + ks * 32);
                mma16816(a0, Ah[ks], B);        mma16816(a1, Ah[ks], B + 2);
                mma16816(a0, Al[ks], B);        mma16816(a1, Al[ks], B + 2);
            }
            // epilogue: packed fp16 z1 stores + BN1 stats (on fp32 accs)
            int mbase = m0 + (lane & 3) * 2;
            #define EPI(J, ACC)                                                       \
                g_z1h[(size_t)(mbase + (mb + J) * 8)     * 64 + cw] = packh2(ACC[0], ACC[2]); \
                g_z1h[(size_t)(mbase + (mb + J) * 8 + 1) * 64 + cw] = packh2(ACC[1], ACC[3]); \
                s1 += ACC[0] + ACC[1];  q1 += ACC[0]*ACC[0] + ACC[1]*ACC[1];          \
                s2 += ACC[2] + ACC[3];  q2 += ACC[2]*ACC[2] + ACC[3]*ACC[3];
            EPI(0, a0)  EPI(1, a1)
            #undef EPI
        }
    }

    // fused layer-1 BN stats: reduce over the 4 lanes sharing each channel
    #pragma unroll
    for (int off = 1; off <= 2; off <<= 1) {
        s1 += __shfl_xor_sync(0xffffffffu, s1, off);
        q1 += __shfl_xor_sync(0xffffffffu, q1, off);
        s2 += __shfl_xor_sync(0xffffffffu, s2, off);
        q2 += __shfl_xor_sync(0xffffffffu, q2, off);
    }
    if ((lane & 3) == 0) {
        int c = n0 + (lane >> 2);
        atomicAdd(&g_stats[128 + c],     (double)s1);
        atomicAdd(&g_stats[256 + c],     (double)q1);
        atomicAdd(&g_stats[128 + c + 8], (double)s2);
        atomicAdd(&g_stats[256 + c + 8], (double)q2);
    }
}

// ---------------- K9: pf1 = relu(a*z1+c) from packed fp16, scatter-max into output ----------------
__global__ void k_relumax1(float* __restrict__ out)
{
    int tid = blockIdx.x * 256 + threadIdx.x;     // NPTS*64 words
    int cw = tid & 63;
    int p  = tid >> 6;
    int c0 = (cw >> 3) * 16 + (cw & 7);           // packed channels c0, c0+8
    uint32_t u = g_z1h[(size_t)p * 64 + cw];      // coalesced read
    float zx, zy;
    unpackh2(u, zx, zy);
    float v0 = fmaxf(fmaf(zx, g_ab[128 + c0],     g_ab[256 + c0]),     0.f);
    float v1 = fmaxf(fmaf(zy, g_ab[128 + c0 + 8], g_ab[256 + c0 + 8]), 0.f);
    unsigned int* dst = (unsigned int*)(out + ((size_t)g_idx[p] << 7) + c0);
    if (v0 > 0.f) atomicMax(dst,     __float_as_uint(v0));
    if (v1 > 0.f) atomicMax(dst + 8, __float_as_uint(v1));
}

// ---------------- launch ----------------
extern "C" void kernel_launch(void* const* d_in, const int* in_sizes, int n_in,
                              void* d_out, int out_size)
{
    const float* feats = (const float*)d_in[0];
    const int*   coors = (const int*)d_in[1];
    const float* W0 = (const float*)d_in[2];
    const float* g0 = (const float*)d_in[3];
    const float* b0 = (const float*)d_in[4];
    const float* W1 = (const float*)d_in[5];
    const float* g1 = (const float*)d_in[6];
    const float* b1 = (const float*)d_in[7];
    (void)in_sizes; (void)n_in;

    void *p_vsum, *p_vcnt, *p_enc0, *p_stats;
    cudaGetSymbolAddress(&p_vsum,  g_vsum);
    cudaGetSymbolAddress(&p_vcnt,  g_vcnt);
    cudaGetSymbolAddress(&p_enc0,  g_enc0);
    cudaGetSymbolAddress(&p_stats, g_stats);

    cudaMemsetAsync(p_vsum,  0, sizeof(float) * CANVAS * 3, 0);
    cudaMemsetAsync(p_vcnt,  0, sizeof(float) * CANVAS, 0);
    cudaMemsetAsync(p_enc0,  0, sizeof(uint32_t) * (size_t)CANVAS * 64, 0);
    cudaMemsetAsync(p_stats, 0, sizeof(double) * 512, 0);
    cudaMemsetAsync(d_out,   0, sizeof(float) * (size_t)out_size, 0);

    k_scatter<<<(NPTS + 255) / 256, 256>>>((const float4*)feats, (const int4*)coors);
    k_feat0<<<NPTS / 128, 128>>>((const float4*)feats, (const int4*)coors, W0);
    k_bnfin<<<1, 128>>>(g0, b0, 64, 0, 0);

    cudaFuncSetAttribute(k_gemm_mma, cudaFuncAttributeMaxDynamicSharedMemorySize, GSMEM);
    k_gemm_mma<<<GGRID, 256, GSMEM>>>(W1);    // 2 CTAs/SM; also BN1 stats

    k_bnfin<<<1, 128>>>(g1, b1, 128, 128, 128);
    k_relumax1<<<(NPTS * 64) / 256, 256>>>((float*)d_out);
}

// round 16
// speedup vs baseline: 1.6209x; 1.0296x over previous
#include <cuda_runtime.h>
#include <cuda_fp16.h>
#include <cstdint>
#include <cstring>

#define NPTS   400000
#define NXG    352
#define NYG    400
#define CANVAS 281600          // 2 * 1 * 400 * 352
#define BNEPS  1e-3f
#define NTILES (NPTS / 128)    // 3125

// ---------------- scratch (static __device__ — no allocation allowed) ----------------
static __device__ int      g_idx[NPTS];
static __device__ float    g_vsum[CANVAS * 3];
static __device__ float    g_vcnt[CANVAS];
static __device__ uint32_t g_z0h[(size_t)NPTS * 32];     // raw z0 as half2: word j = ch 2j,2j+1
static __device__ uint32_t g_enc0[(size_t)CANVAS * 64];  // enc(max raw z0) per voxel
static __device__ uint32_t g_z1h[(size_t)NPTS * 64];     // z1 as half2: word cw = ch (cw>>3)*16+(cw&7), +8
static __device__ double   g_stats[512];                 // s0 q0 s1 q1
static __device__ float    g_ab[384];                    // a0 c0 a1 c1 (folded BN)

// ================= helpers =================
__device__ __forceinline__ uint32_t smem_u32(const void* p) {
    uint32_t a;
    asm("{ .reg .u64 t; cvta.to.shared.u64 t, %1; cvt.u32.u64 %0, t; }" : "=r"(a) : "l"(p));
    return a;
}
// monotone float <-> uint (total order); enc(x) == 0 only for untouched sentinel
__device__ __forceinline__ uint32_t encf(float x) {
    uint32_t b = __float_as_uint(x);
    return (b & 0x80000000u) ? ~b : (b | 0x80000000u);
}
__device__ __forceinline__ float decf(uint32_t u) {
    return __uint_as_float((u & 0x80000000u) ? (u & 0x7FFFFFFFu) : ~u);
}
__device__ __forceinline__ void ldsm_x4(uint32_t* r, uint32_t addr) {
    asm volatile("ldmatrix.sync.aligned.m8n8.x4.shared.b16 {%0,%1,%2,%3}, [%4];"
        : "=r"(r[0]), "=r"(r[1]), "=r"(r[2]), "=r"(r[3]) : "r"(addr));
}
// fp16 mma: m16n8k16, fp32 accumulate
__device__ __forceinline__ void mma16816(float* d, const uint32_t* a, const uint32_t* b) {
    asm volatile("mma.sync.aligned.m16n8k16.row.col.f32.f16.f16.f32 "
        "{%0,%1,%2,%3}, {%4,%5,%6,%7}, {%8,%9}, {%0,%1,%2,%3};"
        : "+f"(d[0]), "+f"(d[1]), "+f"(d[2]), "+f"(d[3])
        : "r"(a[0]), "r"(a[1]), "r"(a[2]), "r"(a[3]), "r"(b[0]), "r"(b[1]));
}
// pack two floats as half2 word
__device__ __forceinline__ uint32_t packh2(float x, float y) {
    __half2 h = __floats2half2_rn(x, y);
    uint32_t u; memcpy(&u, &h, 4); return u;
}
__device__ __forceinline__ void unpackh2(uint32_t u, float& x, float& y) {
    __half2 h; memcpy(&h, &u, 4);
    x = __low2float(h); y = __high2float(h);
}

// ---------------- K1: voxel index + scatter-mean accumulators ----------------
__global__ void k_scatter(const float4* __restrict__ feats, const int4* __restrict__ coors)
{
    int p = blockIdx.x * 256 + threadIdx.x;
    if (p >= NPTS) return;
    int4 c = coors[p];
    int idx = ((c.x + c.y) * NYG + c.z) * NXG + c.w;
    g_idx[p] = idx;
    float4 f = feats[p];
    atomicAdd(&g_vsum[idx * 3 + 0], f.x);
    atomicAdd(&g_vsum[idx * 3 + 1], f.y);
    atomicAdd(&g_vsum[idx * 3 + 2], f.z);
    atomicAdd(&g_vcnt[idx], 1.0f);
}

// ---------------- K2: 10-d feature, z0 = feat @ W0, fused BN0 stats + coalesced raw voxel max ----------------
__global__ void k_feat0(const float4* __restrict__ feats, const int4* __restrict__ coors,
                        const float* __restrict__ W0)
{
    __shared__ float Ws[640];
    __shared__ float outS[128 * 65];
    __shared__ int   sIdxS[128];
    int t  = threadIdx.x;
    int p0 = blockIdx.x * 128;
    for (int i = t; i < 640; i += 128) Ws[i] = W0[i];

    int p = p0 + t;
    int4  c = coors[p];
    float4 f = feats[p];
    int   idx = g_idx[p];
    sIdxS[t] = idx;
    float inv = 1.0f / g_vcnt[idx];
    float mx = g_vsum[idx * 3 + 0] * inv;
    float my = g_vsum[idx * 3 + 1] * inv;
    float mz = g_vsum[idx * 3 + 2] * inv;

    float f10[10];
    f10[0] = f.x;  f10[1] = f.y;  f10[2] = f.z;  f10[3] = f.w;
    f10[4] = f.x - mx;  f10[5] = f.y - my;  f10[6] = f.z - mz;
    f10[7] = f.x - ((float)c.w * 0.2f + 0.1f);
    f10[8] = f.y - ((float)c.z * 0.2f - 39.9f);
    f10[9] = f.z - ((float)c.y * 4.0f - 1.0f);
    __syncthreads();

    #pragma unroll
    for (int j = 0; j < 64; j++) {
        float acc = 0.f;
        #pragma unroll
        for (int k = 0; k < 10; k++) acc = fmaf(f10[k], Ws[k * 64 + j], acc);
        outS[t * 65 + j] = acc;
    }
    __syncthreads();

    // coalesced fp16 z0 store: word 2m,2m+1 = channels 4m..4m+3 (uint2 per slot)
    uint2* gout = (uint2*)(g_z0h + (size_t)p0 * 32);
    #pragma unroll
    for (int it = 0; it < 16; it++) {
        int slot = t + it * 128;                  // 0..2047
        int row = slot >> 4;
        int m4 = (slot & 15) << 2;
        const float* s = &outS[row * 65 + m4];
        gout[slot] = make_uint2(packh2(s[0], s[1]), packh2(s[2], s[3]));
    }

    // coalesced scatter-max of RAW z0 into encoded canvas (warp = 2 points x 16 slots)
    #pragma unroll
    for (int it = 0; it < 16; it++) {
        int slot = t + it * 128;
        int pl = slot >> 4;
        int c4 = (slot & 15) << 2;
        const float* s = &outS[pl * 65 + c4];
        uint32_t* dst = g_enc0 + ((size_t)sIdxS[pl] << 6) + c4;
        atomicMax(dst + 0, encf(s[0]));
        atomicMax(dst + 1, encf(s[1]));
        atomicMax(dst + 2, encf(s[2]));
        atomicMax(dst + 3, encf(s[3]));
    }

    // fused BN0 stats: thread t sums 64 rows of channel (t & 63)
    {
        int ch = t & 63;
        int r0 = (t >> 6) * 64;
        float s = 0.f, q = 0.f;
        #pragma unroll 8
        for (int r = 0; r < 64; r++) {
            float v = outS[(r0 + r) * 65 + ch];
            s += v;
            q = fmaf(v, v, q);
        }
        atomicAdd(&g_stats[ch], (double)s);
        atomicAdd(&g_stats[64 + ch], (double)q);
    }
}

// ---------------- K4/K8: fold BN stats + affine into a*x + c ----------------
__global__ void k_bnfin(const float* __restrict__ gamma, const float* __restrict__ beta,
                        int nch, int s_off, int ab_off)
{
    int c = threadIdx.x;
    if (c >= nch) return;
    double mu  = g_stats[s_off + c] * (1.0 / NPTS);
    double var = g_stats[s_off + nch + c] * (1.0 / NPTS) - mu * mu;
    float rstd = rsqrtf((float)var + BNEPS);
    float a = gamma[c] * rstd;
    g_ab[ab_off + c]       = a;
    g_ab[ab_off + nch + c] = beta[c] - (float)mu * a;
}

// ---------------- K6: fp16 2-term mma.sync GEMM, 2 CTAs/SM, fp16 in/out ----------------
// z1 = feat1 @ W1; W1^T split exactly into fp16 hi+lo (register-resident A);
// feat1 in ONE fp16 plane (B). z0 read as half2 words; z1 stored as half2 words.
#define ROWB    272
#define PLANE   (128 * ROWB)        // 34816
#define FBASE   (2 * PLANE)         // single feat plane after W hi/lo planes
#define GSMEM   (3 * PLANE)         // 104448 (x2 CTAs = 204KB/SM)
#define GGRID   296                 // 2 per SM

__global__ void __launch_bounds__(256, 2) k_gemm_mma(const float* __restrict__ W1)
{
    extern __shared__ char sm[];
    uint32_t sbase = smem_u32(sm);
    int t = threadIdx.x, w = t >> 5, lane = t & 31;
    int n0 = w * 16;

    // one-time: W1^T hi/lo fp16 planes (row n, col k); hi+lo is exact
    for (int i = t; i < 16384; i += 256) {
        int k = i >> 7, n = i & 127;
        float v = W1[i];
        __half h = __float2half_rn(v);
        __half l = __float2half_rn(v - __half2float(h));
        *(__half*)(sm + n * ROWB + 2 * k) = h;
        *(__half*)(sm + PLANE + n * ROWB + 2 * k) = l;
    }
    __syncthreads();

    // weight fragments: registers, persistent across tiles (64 regs)
    uint32_t Ah[8][4], Al[8][4];
    {
        int g = lane >> 3, r8 = lane & 7;
        uint32_t row = (uint32_t)(n0 + (g & 1) * 8 + r8) * ROWB + (uint32_t)((g >> 1) * 16);
        #pragma unroll
        for (int ks = 0; ks < 8; ks++) {
            ldsm_x4(Ah[ks], sbase + row + ks * 32);
            ldsm_x4(Al[ks], sbase + PLANE + row + ks * 32);
        }
    }

    float ba0 = g_ab[2 * lane],     bc0 = g_ab[64 + 2 * lane];
    float ba1 = g_ab[2 * lane + 1], bc1 = g_ab[64 + 2 * lane + 1];

    float s1 = 0.f, q1 = 0.f, s2 = 0.f, q2 = 0.f;

    // ldmatrix.x4 feat addressing: mats 0,1 = mb rows (k halves), mats 2,3 = mb+1 rows
    uint32_t baddr4 = sbase + FBASE
                    + (uint32_t)((lane & 7) * ROWB + ((lane >> 3) & 1) * 16
                               + (lane >> 4) * 8 * ROWB);

    for (int tile = blockIdx.x; tile < NTILES; tile += gridDim.x) {
        int m0 = tile * 128;
        __syncthreads();                          // prev tile's ldsm reads done

        // build single fp16 feat plane, direct LDG, staged in 8-row chunks (reg cap)
        #pragma unroll
        for (int half = 0; half < 2; half++) {
            uint32_t zw[8];
            uint2    gv[8];
            int      idxr[8];
            #pragma unroll
            for (int rr = 0; rr < 8; rr++) {
                int gm = m0 + w * 16 + half * 8 + rr;
                idxr[rr] = g_idx[gm];             // warp-broadcast load
                zw[rr] = g_z0h[(size_t)gm * 32 + lane];   // channels 2lane, 2lane+1
            }
            #pragma unroll
            for (int rr = 0; rr < 8; rr++)
                gv[rr] = *(const uint2*)(g_enc0 + ((size_t)idxr[rr] << 6) + 2 * lane);
            #pragma unroll
            for (int rr = 0; rr < 8; rr++) {
                int r = w * 16 + half * 8 + rr;
                float zx, zy;
                unpackh2(zw[rr], zx, zy);
                float p0 = fmaxf(fmaf(zx, ba0, bc0), 0.f);
                float p1 = fmaxf(fmaf(zy, ba1, bc1), 0.f);
                char* rp = sm + FBASE + r * ROWB + 4 * lane;
                *(uint32_t*)(rp) = packh2(p0, p1);
                float g0f = fmaxf(fmaf(decf(gv[rr].x), ba0, bc0), 0.f);  // occupied only
                float g1f = fmaxf(fmaf(decf(gv[rr].y), ba1, bc1), 0.f);
                *(uint32_t*)(rp + 128) = packh2(g0f, g1f);
            }
        }
        __syncthreads();

        // 2 mb-blocks per iteration: 2 independent accumulator chains, 2 terms each
        int cw = w * 8 + (lane >> 2);             // z1h word index (channels c, c+8)
        #pragma unroll
        for (int mb = 0; mb < 16; mb += 2) {
            float a0[4] = {0,0,0,0}, a1[4] = {0,0,0,0};
            uint32_t ab = baddr4 + (uint32_t)(mb * 8 * ROWB);
            #pragma unroll
            for (int ks = 0; ks < 8; ks++) {
                uint32_t B[4];
                ldsm_x4(B, ab + ks * 32);
                mma16816(a0, Ah[ks], B);        mma16816(a1, Ah[ks], B + 2);
                mma16816(a0, Al[ks], B);        mma16816(a1, Al[ks], B + 2);
            }
            // epilogue: packed fp16 z1 stores + BN1 stats (on fp32 accs)
            int mbase = m0 + (lane & 3) * 2;
            #define EPI(J, ACC)                                                       \
                g_z1h[(size_t)(mbase + (mb + J) * 8)     * 64 + cw] = packh2(ACC[0], ACC[2]); \
                g_z1h[(size_t)(mbase + (mb + J) * 8 + 1) * 64 + cw] = packh2(ACC[1], ACC[3]); \
                s1 += ACC[0] + ACC[1];  q1 += ACC[0]*ACC[0] + ACC[1]*ACC[1];          \
                s2 += ACC[2] + ACC[3];  q2 += ACC[2]*ACC[2] + ACC[3]*ACC[3];
            EPI(0, a0)  EPI(1, a1)
            #undef EPI
        }
    }

    // fused layer-1 BN stats: reduce over the 4 lanes sharing each channel
    #pragma unroll
    for (int off = 1; off <= 2; off <<= 1) {
        s1 += __shfl_xor_sync(0xffffffffu, s1, off);
        q1 += __shfl_xor_sync(0xffffffffu, q1, off);
        s2 += __shfl_xor_sync(0xffffffffu, s2, off);
        q2 += __shfl_xor_sync(0xffffffffu, q2, off);
    }
    if ((lane & 3) == 0) {
        int c = n0 + (lane >> 2);
        atomicAdd(&g_stats[128 + c],     (double)s1);
        atomicAdd(&g_stats[256 + c],     (double)q1);
        atomicAdd(&g_stats[128 + c + 8], (double)s2);
        atomicAdd(&g_stats[256 + c + 8], (double)q2);
    }
}

// ---------------- K9: pf1 = relu(a*z1+c) from packed fp16, scatter-max into output ----------------
__global__ void k_relumax1(float* __restrict__ out)
{
    int tid = blockIdx.x * 256 + threadIdx.x;     // NPTS*64 words
    int cw = tid & 63;
    int p  = tid >> 6;
    int c0 = (cw >> 3) * 16 + (cw & 7);           // packed channels c0, c0+8
    uint32_t u = g_z1h[(size_t)p * 64 + cw];      // coalesced read
    float zx, zy;
    unpackh2(u, zx, zy);
    float v0 = fmaxf(fmaf(zx, g_ab[128 + c0],     g_ab[256 + c0]),     0.f);
    float v1 = fmaxf(fmaf(zy, g_ab[128 + c0 + 8], g_ab[256 + c0 + 8]), 0.f);
    unsigned int* dst = (unsigned int*)(out + ((size_t)g_idx[p] << 7) + c0);
    if (v0 > 0.f) atomicMax(dst,     __float_as_uint(v0));
    if (v1 > 0.f) atomicMax(dst + 8, __float_as_uint(v1));
}

// ---------------- launch ----------------
extern "C" void kernel_launch(void* const* d_in, const int* in_sizes, int n_in,
                              void* d_out, int out_size)
{
    const float* feats = (const float*)d_in[0];
    const int*   coors = (const int*)d_in[1];
    const float* W0 = (const float*)d_in[2];
    const float* g0 = (const float*)d_in[3];
    const float* b0 = (const float*)d_in[4];
    const float* W1 = (const float*)d_in[5];
    const float* g1 = (const float*)d_in[6];
    const float* b1 = (const float*)d_in[7];
    (void)in_sizes; (void)n_in;

    // side stream + events for memset overlap (host-side objects, created once
    // outside capture on the first — uncaptured — correctness call; identical
    // captured work every call)
    static cudaStream_t s_side = nullptr;
    static cudaEvent_t  ev_fork = nullptr, ev_enc = nullptr, ev_out = nullptr;
    if (s_side == nullptr) {
        cudaStreamCreateWithFlags(&s_side, cudaStreamNonBlocking);
        cudaEventCreateWithFlags(&ev_fork, cudaEventDisableTiming);
        cudaEventCreateWithFlags(&ev_enc,  cudaEventDisableTiming);
        cudaEventCreateWithFlags(&ev_out,  cudaEventDisableTiming);
    }

    void *p_vsum, *p_vcnt, *p_enc0, *p_stats;
    cudaGetSymbolAddress(&p_vsum,  g_vsum);
    cudaGetSymbolAddress(&p_vcnt,  g_vcnt);
    cudaGetSymbolAddress(&p_enc0,  g_enc0);
    cudaGetSymbolAddress(&p_stats, g_stats);

    // fork: big memsets on side stream (enc0 overlaps scatter; d_out overlaps feat0+gemm)
    cudaEventRecord(ev_fork, 0);
    cudaStreamWaitEvent(s_side, ev_fork, 0);
    cudaMemsetAsync(p_enc0, 0, sizeof(uint32_t) * (size_t)CANVAS * 64, s_side);
    cudaEventRecord(ev_enc, s_side);
    cudaMemsetAsync(d_out,  0, sizeof(float) * (size_t)out_size, s_side);
    cudaEventRecord(ev_out, s_side);

    // main stream: small memsets + pipeline
    cudaMemsetAsync(p_vsum,  0, sizeof(float) * CANVAS * 3, 0);
    cudaMemsetAsync(p_vcnt,  0, sizeof(float) * CANVAS, 0);
    cudaMemsetAsync(p_stats, 0, sizeof(double) * 512, 0);

    k_scatter<<<(NPTS + 255) / 256, 256>>>((const float4*)feats, (const int4*)coors);
    cudaStreamWaitEvent(0, ev_enc, 0);           // enc0 zeroed before feat0 scatter-max
    k_feat0<<<NPTS / 128, 128>>>((const float4*)feats, (const int4*)coors, W0);
    k_bnfin<<<1, 128>>>(g0, b0, 64, 0, 0);

    cudaFuncSetAttribute(k_gemm_mma, cudaFuncAttributeMaxDynamicSharedMemorySize, GSMEM);
    k_gemm_mma<<<GGRID, 256, GSMEM>>>(W1);    // 2 CTAs/SM; also BN1 stats

    k_bnfin<<<1, 128>>>(g1, b1, 128, 128, 128);
    cudaStreamWaitEvent(0, ev_out, 0);           // d_out zeroed before relumax1
    k_relumax1<<<(NPTS * 64) / 256, 256>>>((float*)d_out);
}